// round 6
// baseline (speedup 1.0000x reference)
#include <cuda_runtime.h>
#include <cstdint>

// ---------------------------------------------------------------------------
// FlashSVDLlamaBlock R6: dup-A smem FFMA2 GEMMs (no pk2 MOV tax),
// batched proj+RoPE GEMM, packed-f32x2 flash attention with __expf.
//   B=2, T=1024, D=2048, H=32, HK=8, DH=64, R=48, RO=RFF=1024, INTER=8192
// Scratch (61 MB, phase-liveness reuse):
//   H [0..4,194,303]: hbuf -> attn -> hbuf -> dr
//   B [4,194,304..8,912,895]: qkvr -> ar -> gr/ur
//   C [8,912,896..15,204,351]: wconcat -> qb/kb/vb -> inner + partials
// ---------------------------------------------------------------------------

#define NTOK 2048
#define DMODEL 2048
#define NH 32
#define NHK 8
#define DHEAD 64
#define RNK 48
#define TSEQ 1024
#define NCHUNK 512

#define OFF_H 0u
#define OFF_B 4194304u
#define OFF_C 8912896u
#define SCRATCH_TOTAL 15204352u

__device__ float g_scratch[SCRATCH_TOTAL];

typedef unsigned long long ull;

// ---- packed f32x2 helpers --------------------------------------------------
__device__ __forceinline__ ull pk2(float v) {
    ull r;
    asm("mov.b64 %0, {%1, %1};" : "=l"(r) : "f"(v));
    return r;
}
__device__ __forceinline__ void fma2(ull& c, ull a, ull b) {
    asm("fma.rn.f32x2 %0, %1, %2, %0;" : "+l"(c) : "l"(a), "l"(b));
}
__device__ __forceinline__ void mul2(ull& c, ull a) {
    asm("mul.rn.f32x2 %0, %0, %1;" : "+l"(c) : "l"(a));
}
__device__ __forceinline__ float2 upk2(ull v) {
    float2 r;
    asm("mov.b64 {%0, %1}, %2;" : "=f"(r.x), "=f"(r.y) : "l"(v));
    return r;
}

// ---------------------------------------------------------------------------
// RMSNorm: one block per token, 256 threads, D=2048
// ---------------------------------------------------------------------------
__global__ void __launch_bounds__(256) rms_kernel(const float* __restrict__ x,
                                                  const float* __restrict__ w,
                                                  float* __restrict__ out) {
    int n = blockIdx.x;
    int tid = threadIdx.x;
    const float4* xr = (const float4*)(x + (size_t)n * DMODEL);
    float4 loc[2];
    float ss = 0.f;
#pragma unroll
    for (int i = 0; i < 2; i++) {
        float4 v = xr[tid + i * 256];
        loc[i] = v;
        ss += v.x * v.x + v.y * v.y + v.z * v.z + v.w * v.w;
    }
#pragma unroll
    for (int off = 16; off; off >>= 1)
        ss += __shfl_xor_sync(0xffffffffu, ss, off);
    __shared__ float red[8];
    if ((tid & 31) == 0) red[tid >> 5] = ss;
    __syncthreads();
    float tot = red[0] + red[1] + red[2] + red[3] + red[4] + red[5] + red[6] + red[7];
    float inv = rsqrtf(tot * (1.0f / (float)DMODEL) + 1e-5f);
    const float4* w4 = (const float4*)w;
    float4* o4 = (float4*)(out + (size_t)n * DMODEL);
#pragma unroll
    for (int i = 0; i < 2; i++) {
        int idx = tid + i * 256;
        float4 wv = w4[idx];
        float4 v = loc[i];
        o4[idx] = make_float4(v.x * inv * wv.x, v.y * inv * wv.y,
                              v.z * inv * wv.z, v.w * inv * wv.w);
    }
}

// ---------------------------------------------------------------------------
// SGEMM 128x128, BK=8, 256 thr, 8x8 micro via f32x2 with DUPLICATED-A smem
// (A pairs ready in smem -> zero pk2 MOVs in the hot loop).
//   C[n,m] = sum_k A[n,k]*W[m,k];  MODE 0: =, 1: +R, 2: +=C
// Split-K via blockIdx.z (range Kt, output rows offset z*gridDim.y*128).
// ---------------------------------------------------------------------------
template <int MODE>
__global__ void __launch_bounds__(256, 2) gemm128(const float* __restrict__ A,
                                                  const float* __restrict__ W,
                                                  const float* __restrict__ R,
                                                  float* __restrict__ C,
                                                  int M, int K, int Kt) {
    __shared__ __align__(16) float Ad[2][8][256];   // duplicated pairs
    __shared__ __align__(16) float Ws[2][8][128];
    int n0 = blockIdx.y * 128, m0 = blockIdx.x * 128;
    int tid = threadIdx.x;
    int tx = tid & 15, ty = tid >> 4;
    int lrow = tid >> 1;
    int lcol = (tid & 1) * 4;
    size_t koff = (size_t)blockIdx.z * Kt;
    const float* Ap = A + (size_t)(n0 + lrow) * K + koff + lcol;
    const float* Wp = W + (size_t)(m0 + lrow) * K + koff + lcol;

    ull acc[8][4];
#pragma unroll
    for (int i = 0; i < 8; i++)
#pragma unroll
        for (int j = 0; j < 4; j++) acc[i][j] = 0ull;

    int nt = Kt >> 3;
    {
        float4 av = *(const float4*)Ap;
        float4 wv = *(const float4*)Wp;
        float a4[4] = {av.x, av.y, av.z, av.w};
        float w4[4] = {wv.x, wv.y, wv.z, wv.w};
#pragma unroll
        for (int i = 0; i < 4; i++) {
            *(float2*)&Ad[0][lcol + i][2 * lrow] = make_float2(a4[i], a4[i]);
            Ws[0][lcol + i][lrow] = w4[i];
        }
    }
    __syncthreads();

    for (int kt = 0; kt < nt; kt++) {
        int cur = kt & 1;
        float4 av2, wv2;
        bool has = (kt + 1 < nt);
        if (has) {
            av2 = *(const float4*)(Ap + (size_t)(kt + 1) * 8);
            wv2 = *(const float4*)(Wp + (size_t)(kt + 1) * 8);
        }
#pragma unroll
        for (int k = 0; k < 8; k++) {
            ulonglong2 aA = *(const ulonglong2*)&Ad[cur][k][8 * ty];
            ulonglong2 aB = *(const ulonglong2*)&Ad[cur][k][8 * ty + 4];
            ulonglong2 aC = *(const ulonglong2*)&Ad[cur][k][128 + 8 * ty];
            ulonglong2 aD = *(const ulonglong2*)&Ad[cur][k][128 + 8 * ty + 4];
            ulonglong2 w0 = *(const ulonglong2*)&Ws[cur][k][tx * 4];
            ulonglong2 w1 = *(const ulonglong2*)&Ws[cur][k][64 + tx * 4];
#define GROW(i, ap)                          \
            fma2(acc[i][0], ap, w0.x);       \
            fma2(acc[i][1], ap, w0.y);       \
            fma2(acc[i][2], ap, w1.x);       \
            fma2(acc[i][3], ap, w1.y);
            GROW(0, aA.x) GROW(1, aA.y) GROW(2, aB.x) GROW(3, aB.y)
            GROW(4, aC.x) GROW(5, aC.y) GROW(6, aD.x) GROW(7, aD.y)
#undef GROW
        }
        if (has) {
            int nxt = cur ^ 1;
            float a4[4] = {av2.x, av2.y, av2.z, av2.w};
            float w4[4] = {wv2.x, wv2.y, wv2.z, wv2.w};
#pragma unroll
            for (int i = 0; i < 4; i++) {
                *(float2*)&Ad[nxt][lcol + i][2 * lrow] = make_float2(a4[i], a4[i]);
                Ws[nxt][lcol + i][lrow] = w4[i];
            }
            __syncthreads();
        }
    }

    int zrow = blockIdx.z * (gridDim.y << 7);
#pragma unroll
    for (int i = 0; i < 8; i++) {
        int n = n0 + (i >> 1) * 32 + (i & 1);  // careful: see mapping below
        // mapping must match GROW order: rows 0..3 -> n0+ty*4+? ; recompute:
        (void)n;
    }
    // NOTE: GROW order pairs rows as (aA.x,aA.y,aB.x,aB.y)=n0+4ty+{0,1,2,3},
    //       (aC..aD)=n0+64+4ty+{0,1,2,3}.
#pragma unroll
    for (int i = 0; i < 8; i++) {
        int n = n0 + (i >> 2) * 64 + ty * 4 + (i & 3);
        size_t base = (size_t)(zrow + n) * M;
        float2 p0 = upk2(acc[i][0]), p1 = upk2(acc[i][1]);
        float2 p2 = upk2(acc[i][2]), p3 = upk2(acc[i][3]);
        float4 lo = make_float4(p0.x, p0.y, p1.x, p1.y);
        float4 hi = make_float4(p2.x, p2.y, p3.x, p3.y);
        float* clo = &C[base + m0 + tx * 4];
        float* chi = &C[base + m0 + 64 + tx * 4];
        if (MODE == 1) {
            const float4 rlo = *(const float4*)&R[base + m0 + tx * 4];
            const float4 rhi = *(const float4*)&R[base + m0 + 64 + tx * 4];
            lo.x += rlo.x; lo.y += rlo.y; lo.z += rlo.z; lo.w += rlo.w;
            hi.x += rhi.x; hi.y += rhi.y; hi.z += rhi.z; hi.w += rhi.w;
        }
        if (MODE == 2) {
            const float4 rlo = *(const float4*)clo;
            const float4 rhi = *(const float4*)chi;
            lo.x += rlo.x; lo.y += rlo.y; lo.z += rlo.z; lo.w += rlo.w;
            hi.x += rhi.x; hi.y += rhi.y; hi.z += rhi.z; hi.w += rhi.w;
        }
        *(float4*)clo = lo;
        *(float4*)chi = hi;
    }
}

// ---------------------------------------------------------------------------
// Fused gate/up GEMM + SiLU, 128(N)x64(M), BK=8, dup-A smem, f32x2.
//   inner[n,m] = silu(Ag·Wg) * (Au·Wu);  K=1024, M=8192
// ---------------------------------------------------------------------------
__global__ void __launch_bounds__(256, 2) gateup_kernel(const float* __restrict__ Ag,
                                                        const float* __restrict__ Au,
                                                        const float* __restrict__ Wg,
                                                        const float* __restrict__ Wu,
                                                        float* __restrict__ C,
                                                        int M, int K) {
    __shared__ __align__(16) float Agd[2][8][256];
    __shared__ __align__(16) float Aud[2][8][256];
    __shared__ __align__(16) float Wgs[2][8][64];
    __shared__ __align__(16) float Wus[2][8][64];
    int n0 = blockIdx.y * 128, m0 = blockIdx.x * 64;
    int tid = threadIdx.x;
    int tx = tid & 15, ty = tid >> 4;
    int lrow = tid >> 1;
    int lcol = (tid & 1) * 4;
    int wrow = (tid & 127) >> 1;
    int wcol = (tid & 1) * 4;
    bool isg = tid < 128;
    const float* Agp = Ag + (size_t)(n0 + lrow) * K + lcol;
    const float* Aup = Au + (size_t)(n0 + lrow) * K + lcol;
    const float* Wp = (isg ? Wg : Wu) + (size_t)(m0 + wrow) * K + wcol;

    ull accg[8][2], accu[8][2];
#pragma unroll
    for (int i = 0; i < 8; i++) {
        accg[i][0] = accg[i][1] = 0ull;
        accu[i][0] = accu[i][1] = 0ull;
    }

    int nt = K >> 3;
    {
        float4 ag = *(const float4*)Agp;
        float4 au = *(const float4*)Aup;
        float4 wv = *(const float4*)Wp;
        float g4[4] = {ag.x, ag.y, ag.z, ag.w};
        float u4[4] = {au.x, au.y, au.z, au.w};
        float w4[4] = {wv.x, wv.y, wv.z, wv.w};
        float* ws = isg ? &Wgs[0][0][0] : &Wus[0][0][0];
#pragma unroll
        for (int i = 0; i < 4; i++) {
            *(float2*)&Agd[0][lcol + i][2 * lrow] = make_float2(g4[i], g4[i]);
            *(float2*)&Aud[0][lcol + i][2 * lrow] = make_float2(u4[i], u4[i]);
            ws[(wcol + i) * 64 + wrow] = w4[i];
        }
    }
    __syncthreads();

    for (int kt = 0; kt < nt; kt++) {
        int cur = kt & 1;
        float4 ag2, au2, wv2;
        bool has = (kt + 1 < nt);
        if (has) {
            ag2 = *(const float4*)(Agp + (size_t)(kt + 1) * 8);
            au2 = *(const float4*)(Aup + (size_t)(kt + 1) * 8);
            wv2 = *(const float4*)(Wp + (size_t)(kt + 1) * 8);
        }
#pragma unroll
        for (int k = 0; k < 8; k++) {
            ulonglong2 gA = *(const ulonglong2*)&Agd[cur][k][8 * ty];
            ulonglong2 gB = *(const ulonglong2*)&Agd[cur][k][8 * ty + 4];
            ulonglong2 gC = *(const ulonglong2*)&Agd[cur][k][128 + 8 * ty];
            ulonglong2 gD = *(const ulonglong2*)&Agd[cur][k][128 + 8 * ty + 4];
            ulonglong2 uA = *(const ulonglong2*)&Aud[cur][k][8 * ty];
            ulonglong2 uB = *(const ulonglong2*)&Aud[cur][k][8 * ty + 4];
            ulonglong2 uC = *(const ulonglong2*)&Aud[cur][k][128 + 8 * ty];
            ulonglong2 uD = *(const ulonglong2*)&Aud[cur][k][128 + 8 * ty + 4];
            ulonglong2 wg = *(const ulonglong2*)&Wgs[cur][k][tx * 4];
            ulonglong2 wu = *(const ulonglong2*)&Wus[cur][k][tx * 4];
#define GUROW(i, gp, up)                     \
            fma2(accg[i][0], gp, wg.x);      \
            fma2(accg[i][1], gp, wg.y);      \
            fma2(accu[i][0], up, wu.x);      \
            fma2(accu[i][1], up, wu.y);
            GUROW(0, gA.x, uA.x) GUROW(1, gA.y, uA.y)
            GUROW(2, gB.x, uB.x) GUROW(3, gB.y, uB.y)
            GUROW(4, gC.x, uC.x) GUROW(5, gC.y, uC.y)
            GUROW(6, gD.x, uD.x) GUROW(7, gD.y, uD.y)
#undef GUROW
        }
        if (has) {
            int nxt = cur ^ 1;
            float g4[4] = {ag2.x, ag2.y, ag2.z, ag2.w};
            float u4[4] = {au2.x, au2.y, au2.z, au2.w};
            float w4[4] = {wv2.x, wv2.y, wv2.z, wv2.w};
            float* ws = isg ? &Wgs[nxt][0][0] : &Wus[nxt][0][0];
#pragma unroll
            for (int i = 0; i < 4; i++) {
                *(float2*)&Agd[nxt][lcol + i][2 * lrow] = make_float2(g4[i], g4[i]);
                *(float2*)&Aud[nxt][lcol + i][2 * lrow] = make_float2(u4[i], u4[i]);
                ws[(wcol + i) * 64 + wrow] = w4[i];
            }
            __syncthreads();
        }
    }

#pragma unroll
    for (int i = 0; i < 8; i++) {
        int n = n0 + (i >> 2) * 64 + ty * 4 + (i & 3);
        float2 gp0 = upk2(accg[i][0]), gp1 = upk2(accg[i][1]);
        float2 up0 = upk2(accu[i][0]), up1 = upk2(accu[i][1]);
        float g[4] = {gp0.x, gp0.y, gp1.x, gp1.y};
        float u[4] = {up0.x, up0.y, up1.x, up1.y};
        float o[4];
#pragma unroll
        for (int j = 0; j < 4; j++) o[j] = (g[j] / (1.0f + __expf(-g[j]))) * u[j];
        *(float4*)&C[(size_t)n * M + m0 + tx * 4] = make_float4(o[0], o[1], o[2], o[3]);
    }
}

// ---------------------------------------------------------------------------
// qkv weight concat: wc = [q_V(1536x2048); k_V(384x2048); v_V(384x2048)]
// ---------------------------------------------------------------------------
__global__ void __launch_bounds__(256) concat_qkv(const float* __restrict__ q,
                                                  const float* __restrict__ k,
                                                  const float* __restrict__ v,
                                                  float* __restrict__ wc) {
    int i = blockIdx.x * 256 + threadIdx.x;    // float4 index, total 1,179,648
    float4 val;
    if (i < 786432) val = ((const float4*)q)[i];
    else if (i < 983040) val = ((const float4*)k)[i - 786432];
    else val = ((const float4*)v)[i - 983040];
    ((float4*)wc)[i] = val;
}

// ---------------------------------------------------------------------------
// split-K reduce: dst[i] = sum_{p<4} part[p*524288 + i]   (512x1024 floats)
// ---------------------------------------------------------------------------
__global__ void __launch_bounds__(256) reduce4_kernel(const float* __restrict__ part,
                                                      float* __restrict__ dst) {
    int i = blockIdx.x * 256 + threadIdx.x;    // float4 index, total 131072
    const float4* p = (const float4*)part;
    float4 a = p[i], b = p[i + 131072], c = p[i + 262144], d = p[i + 393216];
    ((float4*)dst)[i] = make_float4(a.x + b.x + c.x + d.x, a.y + b.y + c.y + d.y,
                                    a.z + b.z + c.z + d.z, a.w + b.w + c.w + d.w);
}

// ---------------------------------------------------------------------------
// Batched per-head Us projection + fused RoPE.
//   For head-slot hidx (0..47): q heads 0..31 (rope), k heads 32..39 (rope),
//   v heads 40..47 (no rope).
//   out[b,hh,t,dh] = sum_r Rv[n, hidx*48+r] * Us[hh,dh,r]
// Block: 128 tokens x 64 dh, 256 threads (tx=dh/8, ty=tok/4), K=48 in smem.
// RoPE partner dh^32 obtained via shfl_xor(tid, 4).
// ---------------------------------------------------------------------------
__global__ void __launch_bounds__(256) proj2_kernel(
    const float* __restrict__ Rv,
    const float* __restrict__ q_Us, const float* __restrict__ k_Us,
    const float* __restrict__ v_Us,
    const int* __restrict__ pos_ids,
    float* __restrict__ qb, float* __restrict__ kb, float* __restrict__ vb) {
    int hidx = blockIdx.y;
    int n0 = blockIdx.x * 128;
    int tid = threadIdx.x;
    __shared__ float Rvs[48][128];
    __shared__ float Uss[48][64];

#pragma unroll
    for (int i = 0; i < 6; i++) {
        int f = tid + i * 256;             // 0..1535
        int r = f / 12, c4 = (f % 12) * 4;
        float4 v = *(const float4*)&Rv[(size_t)(n0 + r) * 2304 + hidx * 48 + c4];
        Rvs[c4 + 0][r] = v.x; Rvs[c4 + 1][r] = v.y;
        Rvs[c4 + 2][r] = v.z; Rvs[c4 + 3][r] = v.w;
    }
    const float* Us = (hidx < 32) ? q_Us + (size_t)hidx * 3072
                    : (hidx < 40) ? k_Us + (size_t)(hidx - 32) * 3072
                                  : v_Us + (size_t)(hidx - 40) * 3072;
#pragma unroll
    for (int i = 0; i < 3; i++) {
        int f = tid + i * 256;             // 0..767
        int dh = f / 12, c4 = (f % 12) * 4;
        float4 v = *(const float4*)&Us[dh * 48 + c4];
        Uss[c4 + 0][dh] = v.x; Uss[c4 + 1][dh] = v.y;
        Uss[c4 + 2][dh] = v.z; Uss[c4 + 3][dh] = v.w;
    }
    __syncthreads();

    int tx = tid & 7;    // dh block: dh = tx*8 + j
    int ty = tid >> 3;   // token block: tok = ty*4 + i
    float acc[4][8];
#pragma unroll
    for (int i = 0; i < 4; i++)
#pragma unroll
        for (int j = 0; j < 8; j++) acc[i][j] = 0.f;

#pragma unroll 8
    for (int k = 0; k < 48; k++) {
        float4 a = *(const float4*)&Rvs[k][ty * 4];
        float4 w0 = *(const float4*)&Uss[k][tx * 8];
        float4 w1 = *(const float4*)&Uss[k][tx * 8 + 4];
        float av[4] = {a.x, a.y, a.z, a.w};
        float wv[8] = {w0.x, w0.y, w0.z, w0.w, w1.x, w1.y, w1.z, w1.w};
#pragma unroll
        for (int i = 0; i < 4; i++)
#pragma unroll
            for (int j = 0; j < 8; j++) acc[i][j] += av[i] * wv[j];
    }

    // partner values (dh ^ 32) live in thread tid^4 of the same warp
    float prt[4][8];
#pragma unroll
    for (int i = 0; i < 4; i++)
#pragma unroll
        for (int j = 0; j < 8; j++)
            prt[i][j] = __shfl_xor_sync(0xffffffffu, acc[i][j], 4);

    bool dorope = (hidx < 40);
    float sgn = (tx < 4) ? -1.f : 1.f;
    float invf[4];
    if (dorope) {
#pragma unroll
        for (int fj = 0; fj < 4; fj++)
            invf[fj] = expf(-(float)(tx * 4 + fj) * (9.210340371976184f / 32.0f));
    }

    float* outp;
    int hh, nh;
    if (hidx < 32)      { outp = qb; hh = hidx;      nh = NH;  }
    else if (hidx < 40) { outp = kb; hh = hidx - 32; nh = NHK; }
    else                { outp = vb; hh = hidx - 40; nh = NHK; }

#pragma unroll
    for (int i = 0; i < 4; i++) {
        int n = n0 + ty * 4 + i;
        int b = n >> 10;
        int t = n & 1023;
        float vals[8];
        if (dorope) {
            float pos = (float)pos_ids[t];
#pragma unroll
            for (int fj = 0; fj < 4; fj++) {
                float ang = pos * invf[fj];
                float c = cosf(ang), s = sinf(ang);
                vals[fj * 2 + 0] = acc[i][fj * 2 + 0] * c + sgn * prt[i][fj * 2 + 0] * s;
                vals[fj * 2 + 1] = acc[i][fj * 2 + 1] * c + sgn * prt[i][fj * 2 + 1] * s;
            }
        } else {
#pragma unroll
            for (int j = 0; j < 8; j++) vals[j] = acc[i][j];
        }
        float* op = outp + (((size_t)b * nh + hh) * TSEQ + t) * DHEAD + tx * 8;
        *(float4*)op       = make_float4(vals[0], vals[1], vals[2], vals[3]);
        *(float4*)(op + 4) = make_float4(vals[4], vals[5], vals[6], vals[7]);
    }
}

// ---------------------------------------------------------------------------
// Causal flash attention, fp32 packed f32x2 + __expf.
// One query/thread, 128 q/block. GQA hk=h/4. Out: attn[b, t, h*64+d]
// ---------------------------------------------------------------------------
__global__ void __launch_bounds__(128) flash_kernel(const float* __restrict__ Q,
                                                    const float* __restrict__ Kg,
                                                    const float* __restrict__ Vg,
                                                    float* __restrict__ Out) {
    int bh = blockIdx.y;
    int b = bh >> 5;
    int h = bh & 31;
    int hk = h >> 2;
    int q0 = blockIdx.x * 128;
    int tid = threadIdx.x;
    int qi = q0 + tid;

    __shared__ __align__(16) float Ks[32][64];
    __shared__ __align__(16) float Vs[32][64];

    ull q2[32];
    const float* qp = Q + (((size_t)b * NH + h) * TSEQ + qi) * DHEAD;
#pragma unroll
    for (int c = 0; c < 16; c++) {
        ulonglong2 t = *(const ulonglong2*)(qp + c * 4);
        q2[c * 2] = t.x; q2[c * 2 + 1] = t.y;
    }
    float m = -1e30f, l = 0.f;
    ull o2[32];
#pragma unroll
    for (int d = 0; d < 32; d++) o2[d] = 0ull;

    const float* kbase = Kg + (((size_t)b * NHK + hk) * TSEQ) * DHEAD;
    const float* vbase = Vg + (((size_t)b * NHK + hk) * TSEQ) * DHEAD;
    int nkt = (q0 + 128) / 32;

    for (int kt = 0; kt < nkt; kt++) {
        int kstart = kt * 32;
        __syncthreads();
#pragma unroll
        for (int i = 0; i < 4; i++) {
            int e = tid + i * 128;
            int row = e >> 4;
            int col = (e & 15) * 4;
            *(float4*)&Ks[row][col] = *(const float4*)(kbase + (size_t)(kstart + row) * 64 + col);
            *(float4*)&Vs[row][col] = *(const float4*)(vbase + (size_t)(kstart + row) * 64 + col);
        }
        __syncthreads();

        float s[32];
#pragma unroll
        for (int j = 0; j < 32; j++) {
            ull a0 = 0ull, a1 = 0ull, a2 = 0ull, a3 = 0ull;
#pragma unroll
            for (int c = 0; c < 8; c++) {
                ulonglong2 k01 = *(const ulonglong2*)&Ks[j][c * 8];
                ulonglong2 k23 = *(const ulonglong2*)&Ks[j][c * 8 + 4];
                fma2(a0, q2[c * 4 + 0], k01.x);
                fma2(a1, q2[c * 4 + 1], k01.y);
                fma2(a2, q2[c * 4 + 2], k23.x);
                fma2(a3, q2[c * 4 + 3], k23.y);
            }
            float2 f0 = upk2(a0), f1 = upk2(a1), f2 = upk2(a2), f3 = upk2(a3);
            float acc = ((f0.x + f0.y) + (f1.x + f1.y)) +
                        ((f2.x + f2.y) + (f3.x + f3.y));
            s[j] = (kstart + j <= qi) ? acc * 0.125f : -1e30f;
        }
        float mt = m;
#pragma unroll
        for (int j = 0; j < 32; j++) mt = fmaxf(mt, s[j]);
        float corr = __expf(m - mt);
        m = mt;
        l *= corr;
        ull c2 = pk2(corr);
#pragma unroll
        for (int d = 0; d < 32; d++) mul2(o2[d], c2);
#pragma unroll
        for (int j = 0; j < 32; j++) {
            float p = __expf(s[j] - m);
            l += p;
            ull p2 = pk2(p);
#pragma unroll
            for (int c = 0; c < 8; c++) {
                ulonglong2 v01 = *(const ulonglong2*)&Vs[j][c * 8];
                ulonglong2 v23 = *(const ulonglong2*)&Vs[j][c * 8 + 4];
                fma2(o2[c * 4 + 0], p2, v01.x);
                fma2(o2[c * 4 + 1], p2, v01.y);
                fma2(o2[c * 4 + 2], p2, v23.x);
                fma2(o2[c * 4 + 3], p2, v23.y);
            }
        }
    }
    float invl = 1.0f / l;
    float* op = Out + ((size_t)b * TSEQ + qi) * DMODEL + h * DHEAD;
#pragma unroll
    for (int d = 0; d < 32; d++) {
        float2 v = upk2(o2[d]);
        *(float2*)(op + d * 2) = make_float2(v.x * invl, v.y * invl);
    }
}

// ---------------------------------------------------------------------------
// Launch
// ---------------------------------------------------------------------------
extern "C" void kernel_launch(void* const* d_in, const int* in_sizes, int n_in,
                              void* d_out, int out_size) {
    const float* x     = (const float*)d_in[0];
    const int*   pos   = (const int*)d_in[1];
    const float* ln1   = (const float*)d_in[2];
    const float* ln2   = (const float*)d_in[3];
    const float* q_Us  = (const float*)d_in[4];
    const float* q_V   = (const float*)d_in[5];
    const float* k_Us  = (const float*)d_in[6];
    const float* k_V   = (const float*)d_in[7];
    const float* v_Us  = (const float*)d_in[8];
    const float* v_V   = (const float*)d_in[9];
    const float* o_Us  = (const float*)d_in[10];
    const float* o_V   = (const float*)d_in[11];
    const float* g_Us  = (const float*)d_in[12];
    const float* g_V   = (const float*)d_in[13];
    const float* u_Us  = (const float*)d_in[14];
    const float* u_V   = (const float*)d_in[15];
    const float* d_Us  = (const float*)d_in[16];
    const float* d_V   = (const float*)d_in[17];
    float* out = (float*)d_out;

    float* S = nullptr;
    cudaGetSymbolAddress((void**)&S, g_scratch);
    float* H  = S + OFF_H;
    float* Bb = S + OFF_B;
    float* C  = S + OFF_C;

    float* hbuf  = H;
    float* wc    = C;                        // 2304x2048
    float* qkvr  = Bb;                       // 2048x2304
    float* qb    = C;                        // 2*32*1024*64   (wc dead)
    float* kb    = C + 4194304;              // 2*8*1024*64
    float* vb    = C + 5242880;              // 2*8*1024*64
    float* attn  = H;                        // 2048x2048      (hbuf dead)
    float* ar    = Bb;                       // 2048x1024      (qkvr dead)
    float* gr    = Bb;                       // 2048x1024      (ar dead)
    float* ur    = Bb + 2097152;             // 2048x1024
    float* inner = C;                        // 512x8192       (qb/kb/vb dead)
    float* part  = C + 4194304;              // 4 x 512x1024
    float* dr    = H;                        // 2048x1024      (hbuf dead)

    // ---- attention sub-block ----
    rms_kernel<<<NTOK, 256>>>(x, ln1, hbuf);
    concat_qkv<<<4608, 256>>>(q_V, k_V, v_V, wc);
    gemm128<0><<<dim3(18, 16), 256>>>(hbuf, wc, nullptr, qkvr, 2304, 2048, 2048);
    proj2_kernel<<<dim3(16, 48), 256>>>(qkvr, q_Us, k_Us, v_Us, pos, qb, kb, vb);
    flash_kernel<<<dim3(8, 64), 128>>>(qb, kb, vb, attn);
    gemm128<0><<<dim3(8, 16), 256>>>(attn, o_V, nullptr, ar, 1024, 2048, 2048);
    gemm128<1><<<dim3(16, 16), 256>>>(ar, o_Us, x, out, 2048, 1024, 1024);

    // ---- MLP sub-block ----
    rms_kernel<<<NTOK, 256>>>(out, ln2, hbuf);
    gemm128<0><<<dim3(8, 16), 256>>>(hbuf, g_V, nullptr, gr, 1024, 2048, 2048);
    gemm128<0><<<dim3(8, 16), 256>>>(hbuf, u_V, nullptr, ur, 1024, 2048, 2048);

    for (int c = 0; c < NTOK / NCHUNK; c++) {
        const float* grc = gr + (size_t)c * NCHUNK * 1024;
        const float* urc = ur + (size_t)c * NCHUNK * 1024;
        gateup_kernel<<<dim3(128, 4), 256>>>(grc, urc, g_Us, u_Us, inner, 8192, 1024);
        gemm128<0><<<dim3(8, 4, 4), 256>>>(inner, d_V, nullptr, part, 1024, 8192, 2048);
        reduce4_kernel<<<512, 256>>>(part, dr + (size_t)c * NCHUNK * 1024);
    }
    gemm128<2><<<dim3(16, 16), 256>>>(dr, d_Us, nullptr, out, 2048, 1024, 1024);
}

// round 9
// speedup vs baseline: 1.3030x; 1.3030x over previous
#include <cuda_runtime.h>
#include <cstdint>

// ---------------------------------------------------------------------------
// FlashSVDLlamaBlock R8 (= R7 resubmit; R7 was an infra failure, never ran):
// R5 GEMMs (LDS-roofline 8x8 f32x2, pk2-in-loop) + R6 proj2 (batched
// proj+RoPE) + R6 packed-f32x2 flash attention.
//   B=2, T=1024, D=2048, H=32, HK=8, DH=64, R=48, RO=RFF=1024, INTER=8192
// Scratch (61 MB, phase-liveness reuse):
//   H [0..4,194,303]: hbuf -> attn -> hbuf -> dr
//   B [4,194,304..8,912,895]: qkvr -> ar -> gr/ur
//   C [8,912,896..15,204,351]: wconcat -> qb/kb/vb -> inner + partials
// ---------------------------------------------------------------------------

#define NTOK 2048
#define DMODEL 2048
#define NH 32
#define NHK 8
#define DHEAD 64
#define RNK 48
#define TSEQ 1024
#define NCHUNK 512

#define OFF_H 0u
#define OFF_B 4194304u
#define OFF_C 8912896u
#define SCRATCH_TOTAL 15204352u

__device__ float g_scratch[SCRATCH_TOTAL];

typedef unsigned long long ull;

// ---- packed f32x2 helpers --------------------------------------------------
__device__ __forceinline__ ull pk2(float v) {
    ull r;
    asm("mov.b64 %0, {%1, %1};" : "=l"(r) : "f"(v));
    return r;
}
__device__ __forceinline__ void fma2(ull& c, ull a, ull b) {
    asm("fma.rn.f32x2 %0, %1, %2, %0;" : "+l"(c) : "l"(a), "l"(b));
}
__device__ __forceinline__ void mul2(ull& c, ull a) {
    asm("mul.rn.f32x2 %0, %0, %1;" : "+l"(c) : "l"(a));
}
__device__ __forceinline__ float2 upk2(ull v) {
    float2 r;
    asm("mov.b64 {%0, %1}, %2;" : "=f"(r.x), "=f"(r.y) : "l"(v));
    return r;
}

// ---------------------------------------------------------------------------
// RMSNorm
// ---------------------------------------------------------------------------
__global__ void __launch_bounds__(256) rms_kernel(const float* __restrict__ x,
                                                  const float* __restrict__ w,
                                                  float* __restrict__ out) {
    int n = blockIdx.x;
    int tid = threadIdx.x;
    const float4* xr = (const float4*)(x + (size_t)n * DMODEL);
    float4 loc[2];
    float ss = 0.f;
#pragma unroll
    for (int i = 0; i < 2; i++) {
        float4 v = xr[tid + i * 256];
        loc[i] = v;
        ss += v.x * v.x + v.y * v.y + v.z * v.z + v.w * v.w;
    }
#pragma unroll
    for (int off = 16; off; off >>= 1)
        ss += __shfl_xor_sync(0xffffffffu, ss, off);
    __shared__ float red[8];
    if ((tid & 31) == 0) red[tid >> 5] = ss;
    __syncthreads();
    float tot = red[0] + red[1] + red[2] + red[3] + red[4] + red[5] + red[6] + red[7];
    float inv = rsqrtf(tot * (1.0f / (float)DMODEL) + 1e-5f);
    const float4* w4 = (const float4*)w;
    float4* o4 = (float4*)(out + (size_t)n * DMODEL);
#pragma unroll
    for (int i = 0; i < 2; i++) {
        int idx = tid + i * 256;
        float4 wv = w4[idx];
        float4 v = loc[i];
        o4[idx] = make_float4(v.x * inv * wv.x, v.y * inv * wv.y,
                              v.z * inv * wv.z, v.w * inv * wv.w);
    }
}

// ---------------------------------------------------------------------------
// SGEMM 128x128, BK=8, 256 thr, 8x8 micro via f32x2, double-buffered.
// (R5 version: 1.0 B/MAC smem traffic — LDS/FMA co-bound roofline.)
//   C[n,m] = sum_k A[n,k]*W[m,k];  MODE 0: =, 1: +R, 2: +=C
// Split-K via blockIdx.z (range Kt, output rows offset z*gridDim.y*128).
// ---------------------------------------------------------------------------
template <int MODE>
__global__ void __launch_bounds__(256, 2) gemm128(const float* __restrict__ A,
                                                  const float* __restrict__ W,
                                                  const float* __restrict__ R,
                                                  float* __restrict__ C,
                                                  int M, int K, int Kt) {
    __shared__ __align__(16) float As[2][8][128];
    __shared__ __align__(16) float Ws[2][8][128];
    int n0 = blockIdx.y * 128, m0 = blockIdx.x * 128;
    int tid = threadIdx.x;
    int tx = tid & 15, ty = tid >> 4;
    int lrow = tid >> 1;
    int lcol = (tid & 1) * 4;
    size_t koff = (size_t)blockIdx.z * Kt;
    const float* Ap = A + (size_t)(n0 + lrow) * K + koff + lcol;
    const float* Wp = W + (size_t)(m0 + lrow) * K + koff + lcol;

    ull acc[8][4];
#pragma unroll
    for (int i = 0; i < 8; i++)
#pragma unroll
        for (int j = 0; j < 4; j++) acc[i][j] = 0ull;

    int nt = Kt >> 3;
    float4 av = *(const float4*)Ap;
    float4 wv = *(const float4*)Wp;
    As[0][lcol + 0][lrow] = av.x; As[0][lcol + 1][lrow] = av.y;
    As[0][lcol + 2][lrow] = av.z; As[0][lcol + 3][lrow] = av.w;
    Ws[0][lcol + 0][lrow] = wv.x; Ws[0][lcol + 1][lrow] = wv.y;
    Ws[0][lcol + 2][lrow] = wv.z; Ws[0][lcol + 3][lrow] = wv.w;
    __syncthreads();

    for (int kt = 0; kt < nt; kt++) {
        int cur = kt & 1;
        float4 av2, wv2;
        bool has = (kt + 1 < nt);
        if (has) {
            av2 = *(const float4*)(Ap + (size_t)(kt + 1) * 8);
            wv2 = *(const float4*)(Wp + (size_t)(kt + 1) * 8);
        }
#pragma unroll
        for (int k = 0; k < 8; k++) {
            float4 a0 = *(const float4*)&As[cur][k][ty * 4];
            float4 a1 = *(const float4*)&As[cur][k][64 + ty * 4];
            ulonglong2 w0 = *(const ulonglong2*)&Ws[cur][k][tx * 4];
            ulonglong2 w1 = *(const ulonglong2*)&Ws[cur][k][64 + tx * 4];
#define GROW(i, aval)                                   \
            {                                           \
                ull ap = pk2(aval);                     \
                fma2(acc[i][0], ap, w0.x);              \
                fma2(acc[i][1], ap, w0.y);              \
                fma2(acc[i][2], ap, w1.x);              \
                fma2(acc[i][3], ap, w1.y);              \
            }
            GROW(0, a0.x) GROW(1, a0.y) GROW(2, a0.z) GROW(3, a0.w)
            GROW(4, a1.x) GROW(5, a1.y) GROW(6, a1.z) GROW(7, a1.w)
#undef GROW
        }
        if (has) {
            int nxt = cur ^ 1;
            As[nxt][lcol + 0][lrow] = av2.x; As[nxt][lcol + 1][lrow] = av2.y;
            As[nxt][lcol + 2][lrow] = av2.z; As[nxt][lcol + 3][lrow] = av2.w;
            Ws[nxt][lcol + 0][lrow] = wv2.x; Ws[nxt][lcol + 1][lrow] = wv2.y;
            Ws[nxt][lcol + 2][lrow] = wv2.z; Ws[nxt][lcol + 3][lrow] = wv2.w;
            __syncthreads();
        }
    }

    int zrow = blockIdx.z * (gridDim.y << 7);
#pragma unroll
    for (int i = 0; i < 8; i++) {
        int n = n0 + (i >> 2) * 64 + ty * 4 + (i & 3);
        size_t base = (size_t)(zrow + n) * M;
        float2 p0 = upk2(acc[i][0]), p1 = upk2(acc[i][1]);
        float2 p2 = upk2(acc[i][2]), p3 = upk2(acc[i][3]);
        float4 lo = make_float4(p0.x, p0.y, p1.x, p1.y);
        float4 hi = make_float4(p2.x, p2.y, p3.x, p3.y);
        float* clo = &C[base + m0 + tx * 4];
        float* chi = &C[base + m0 + 64 + tx * 4];
        if (MODE == 1) {
            const float4 rlo = *(const float4*)&R[base + m0 + tx * 4];
            const float4 rhi = *(const float4*)&R[base + m0 + 64 + tx * 4];
            lo.x += rlo.x; lo.y += rlo.y; lo.z += rlo.z; lo.w += rlo.w;
            hi.x += rhi.x; hi.y += rhi.y; hi.z += rhi.z; hi.w += rhi.w;
        }
        if (MODE == 2) {
            const float4 rlo = *(const float4*)clo;
            const float4 rhi = *(const float4*)chi;
            lo.x += rlo.x; lo.y += rlo.y; lo.z += rlo.z; lo.w += rlo.w;
            hi.x += rhi.x; hi.y += rhi.y; hi.z += rhi.z; hi.w += rhi.w;
        }
        *(float4*)clo = lo;
        *(float4*)chi = hi;
    }
}

// ---------------------------------------------------------------------------
// Fused gate/up GEMM + SiLU, 128(N)x64(M), BK=8, 8x4 micro via f32x2.
// (R5 version.)  inner[n,m] = silu(Ag·Wg) * (Au·Wu);  K=1024, M=8192
// ---------------------------------------------------------------------------
__global__ void __launch_bounds__(256, 2) gateup_kernel(const float* __restrict__ Ag,
                                                        const float* __restrict__ Au,
                                                        const float* __restrict__ Wg,
                                                        const float* __restrict__ Wu,
                                                        float* __restrict__ C,
                                                        int M, int K) {
    __shared__ __align__(16) float Ags[2][8][128];
    __shared__ __align__(16) float Aus[2][8][128];
    __shared__ __align__(16) float Wgs[2][8][64];
    __shared__ __align__(16) float Wus[2][8][64];
    int n0 = blockIdx.y * 128, m0 = blockIdx.x * 64;
    int tid = threadIdx.x;
    int tx = tid & 15, ty = tid >> 4;
    int lrow = tid >> 1;
    int lcol = (tid & 1) * 4;
    int wrow = (tid & 127) >> 1;
    int wcol = (tid & 1) * 4;
    bool isg = tid < 128;
    const float* Agp = Ag + (size_t)(n0 + lrow) * K + lcol;
    const float* Aup = Au + (size_t)(n0 + lrow) * K + lcol;
    const float* Wp = (isg ? Wg : Wu) + (size_t)(m0 + wrow) * K + wcol;

    ull accg[8][2], accu[8][2];
#pragma unroll
    for (int i = 0; i < 8; i++) {
        accg[i][0] = accg[i][1] = 0ull;
        accu[i][0] = accu[i][1] = 0ull;
    }

    int nt = K >> 3;
    float4 ag = *(const float4*)Agp;
    float4 au = *(const float4*)Aup;
    float4 wv = *(const float4*)Wp;
    Ags[0][lcol + 0][lrow] = ag.x; Ags[0][lcol + 1][lrow] = ag.y;
    Ags[0][lcol + 2][lrow] = ag.z; Ags[0][lcol + 3][lrow] = ag.w;
    Aus[0][lcol + 0][lrow] = au.x; Aus[0][lcol + 1][lrow] = au.y;
    Aus[0][lcol + 2][lrow] = au.z; Aus[0][lcol + 3][lrow] = au.w;
    {
        float* ws = isg ? &Wgs[0][0][0] : &Wus[0][0][0];
        ws[(wcol + 0) * 64 + wrow] = wv.x; ws[(wcol + 1) * 64 + wrow] = wv.y;
        ws[(wcol + 2) * 64 + wrow] = wv.z; ws[(wcol + 3) * 64 + wrow] = wv.w;
    }
    __syncthreads();

    for (int kt = 0; kt < nt; kt++) {
        int cur = kt & 1;
        float4 ag2, au2, wv2;
        bool has = (kt + 1 < nt);
        if (has) {
            ag2 = *(const float4*)(Agp + (size_t)(kt + 1) * 8);
            au2 = *(const float4*)(Aup + (size_t)(kt + 1) * 8);
            wv2 = *(const float4*)(Wp + (size_t)(kt + 1) * 8);
        }
#pragma unroll
        for (int k = 0; k < 8; k++) {
            float4 g0 = *(const float4*)&Ags[cur][k][ty * 4];
            float4 g1 = *(const float4*)&Ags[cur][k][64 + ty * 4];
            float4 u0 = *(const float4*)&Aus[cur][k][ty * 4];
            float4 u1 = *(const float4*)&Aus[cur][k][64 + ty * 4];
            ulonglong2 wg = *(const ulonglong2*)&Wgs[cur][k][tx * 4];
            ulonglong2 wu = *(const ulonglong2*)&Wus[cur][k][tx * 4];
#define GUROW(i, gv, uv)                                  \
            {                                             \
                ull apg = pk2(gv);                        \
                ull apu = pk2(uv);                        \
                fma2(accg[i][0], apg, wg.x);              \
                fma2(accg[i][1], apg, wg.y);              \
                fma2(accu[i][0], apu, wu.x);              \
                fma2(accu[i][1], apu, wu.y);              \
            }
            GUROW(0, g0.x, u0.x) GUROW(1, g0.y, u0.y)
            GUROW(2, g0.z, u0.z) GUROW(3, g0.w, u0.w)
            GUROW(4, g1.x, u1.x) GUROW(5, g1.y, u1.y)
            GUROW(6, g1.z, u1.z) GUROW(7, g1.w, u1.w)
#undef GUROW
        }
        if (has) {
            int nxt = cur ^ 1;
            Ags[nxt][lcol + 0][lrow] = ag2.x; Ags[nxt][lcol + 1][lrow] = ag2.y;
            Ags[nxt][lcol + 2][lrow] = ag2.z; Ags[nxt][lcol + 3][lrow] = ag2.w;
            Aus[nxt][lcol + 0][lrow] = au2.x; Aus[nxt][lcol + 1][lrow] = au2.y;
            Aus[nxt][lcol + 2][lrow] = au2.z; Aus[nxt][lcol + 3][lrow] = au2.w;
            float* ws = isg ? &Wgs[nxt][0][0] : &Wus[nxt][0][0];
            ws[(wcol + 0) * 64 + wrow] = wv2.x; ws[(wcol + 1) * 64 + wrow] = wv2.y;
            ws[(wcol + 2) * 64 + wrow] = wv2.z; ws[(wcol + 3) * 64 + wrow] = wv2.w;
            __syncthreads();
        }
    }

#pragma unroll
    for (int i = 0; i < 8; i++) {
        int n = n0 + (i >> 2) * 64 + ty * 4 + (i & 3);
        float2 gp0 = upk2(accg[i][0]), gp1 = upk2(accg[i][1]);
        float2 up0 = upk2(accu[i][0]), up1 = upk2(accu[i][1]);
        float g[4] = {gp0.x, gp0.y, gp1.x, gp1.y};
        float u[4] = {up0.x, up0.y, up1.x, up1.y};
        float o[4];
#pragma unroll
        for (int j = 0; j < 4; j++) o[j] = (g[j] / (1.0f + __expf(-g[j]))) * u[j];
        *(float4*)&C[(size_t)n * M + m0 + tx * 4] = make_float4(o[0], o[1], o[2], o[3]);
    }
}

// ---------------------------------------------------------------------------
// qkv weight concat: wc = [q_V(1536x2048); k_V(384x2048); v_V(384x2048)]
// ---------------------------------------------------------------------------
__global__ void __launch_bounds__(256) concat_qkv(const float* __restrict__ q,
                                                  const float* __restrict__ k,
                                                  const float* __restrict__ v,
                                                  float* __restrict__ wc) {
    int i = blockIdx.x * 256 + threadIdx.x;
    float4 val;
    if (i < 786432) val = ((const float4*)q)[i];
    else if (i < 983040) val = ((const float4*)k)[i - 786432];
    else val = ((const float4*)v)[i - 983040];
    ((float4*)wc)[i] = val;
}

// ---------------------------------------------------------------------------
// split-K reduce: dst[i] = sum_{p<4} part[p*524288 + i]   (512x1024 floats)
// ---------------------------------------------------------------------------
__global__ void __launch_bounds__(256) reduce4_kernel(const float* __restrict__ part,
                                                      float* __restrict__ dst) {
    int i = blockIdx.x * 256 + threadIdx.x;
    const float4* p = (const float4*)part;
    float4 a = p[i], b = p[i + 131072], c = p[i + 262144], d = p[i + 393216];
    ((float4*)dst)[i] = make_float4(a.x + b.x + c.x + d.x, a.y + b.y + c.y + d.y,
                                    a.z + b.z + c.z + d.z, a.w + b.w + c.w + d.w);
}

// ---------------------------------------------------------------------------
// Batched per-head Us projection + fused RoPE (R6 version, 530us -> 48us).
// Block: 128 tokens x 64 dh, 256 threads, K=48 in smem.
// ---------------------------------------------------------------------------
__global__ void __launch_bounds__(256) proj2_kernel(
    const float* __restrict__ Rv,
    const float* __restrict__ q_Us, const float* __restrict__ k_Us,
    const float* __restrict__ v_Us,
    const int* __restrict__ pos_ids,
    float* __restrict__ qb, float* __restrict__ kb, float* __restrict__ vb) {
    int hidx = blockIdx.y;
    int n0 = blockIdx.x * 128;
    int tid = threadIdx.x;
    __shared__ float Rvs[48][128];
    __shared__ float Uss[48][64];

#pragma unroll
    for (int i = 0; i < 6; i++) {
        int f = tid + i * 256;
        int r = f / 12, c4 = (f % 12) * 4;
        float4 v = *(const float4*)&Rv[(size_t)(n0 + r) * 2304 + hidx * 48 + c4];
        Rvs[c4 + 0][r] = v.x; Rvs[c4 + 1][r] = v.y;
        Rvs[c4 + 2][r] = v.z; Rvs[c4 + 3][r] = v.w;
    }
    const float* Us = (hidx < 32) ? q_Us + (size_t)hidx * 3072
                    : (hidx < 40) ? k_Us + (size_t)(hidx - 32) * 3072
                                  : v_Us + (size_t)(hidx - 40) * 3072;
#pragma unroll
    for (int i = 0; i < 3; i++) {
        int f = tid + i * 256;
        int dh = f / 12, c4 = (f % 12) * 4;
        float4 v = *(const float4*)&Us[dh * 48 + c4];
        Uss[c4 + 0][dh] = v.x; Uss[c4 + 1][dh] = v.y;
        Uss[c4 + 2][dh] = v.z; Uss[c4 + 3][dh] = v.w;
    }
    __syncthreads();

    int tx = tid & 7;
    int ty = tid >> 3;
    float acc[4][8];
#pragma unroll
    for (int i = 0; i < 4; i++)
#pragma unroll
        for (int j = 0; j < 8; j++) acc[i][j] = 0.f;

#pragma unroll 8
    for (int k = 0; k < 48; k++) {
        float4 a = *(const float4*)&Rvs[k][ty * 4];
        float4 w0 = *(const float4*)&Uss[k][tx * 8];
        float4 w1 = *(const float4*)&Uss[k][tx * 8 + 4];
        float av[4] = {a.x, a.y, a.z, a.w};
        float wv[8] = {w0.x, w0.y, w0.z, w0.w, w1.x, w1.y, w1.z, w1.w};
#pragma unroll
        for (int i = 0; i < 4; i++)
#pragma unroll
            for (int j = 0; j < 8; j++) acc[i][j] += av[i] * wv[j];
    }

    float prt[4][8];
#pragma unroll
    for (int i = 0; i < 4; i++)
#pragma unroll
        for (int j = 0; j < 8; j++)
            prt[i][j] = __shfl_xor_sync(0xffffffffu, acc[i][j], 4);

    bool dorope = (hidx < 40);
    float sgn = (tx < 4) ? -1.f : 1.f;
    float invf[4];
    if (dorope) {
#pragma unroll
        for (int fj = 0; fj < 4; fj++)
            invf[fj] = expf(-(float)(tx * 4 + fj) * (9.210340371976184f / 32.0f));
    }

    float* outp;
    int hh, nh;
    if (hidx < 32)      { outp = qb; hh = hidx;      nh = NH;  }
    else if (hidx < 40) { outp = kb; hh = hidx - 32; nh = NHK; }
    else                { outp = vb; hh = hidx - 40; nh = NHK; }

#pragma unroll
    for (int i = 0; i < 4; i++) {
        int n = n0 + ty * 4 + i;
        int b = n >> 10;
        int t = n & 1023;
        float vals[8];
        if (dorope) {
            float pos = (float)pos_ids[t];
#pragma unroll
            for (int fj = 0; fj < 4; fj++) {
                float ang = pos * invf[fj];
                float c = cosf(ang), s = sinf(ang);
                vals[fj * 2 + 0] = acc[i][fj * 2 + 0] * c + sgn * prt[i][fj * 2 + 0] * s;
                vals[fj * 2 + 1] = acc[i][fj * 2 + 1] * c + sgn * prt[i][fj * 2 + 1] * s;
            }
        } else {
#pragma unroll
            for (int j = 0; j < 8; j++) vals[j] = acc[i][j];
        }
        float* op = outp + (((size_t)b * nh + hh) * TSEQ + t) * DHEAD + tx * 8;
        *(float4*)op       = make_float4(vals[0], vals[1], vals[2], vals[3]);
        *(float4*)(op + 4) = make_float4(vals[4], vals[5], vals[6], vals[7]);
    }
}

// ---------------------------------------------------------------------------
// Causal flash attention, packed f32x2 + __expf (R6 version).
// One query/thread, 128 q/block. GQA hk=h/4. Out: attn[b, t, h*64+d]
// ---------------------------------------------------------------------------
__global__ void __launch_bounds__(128) flash_kernel(const float* __restrict__ Q,
                                                    const float* __restrict__ Kg,
                                                    const float* __restrict__ Vg,
                                                    float* __restrict__ Out) {
    int bh = blockIdx.y;
    int b = bh >> 5;
    int h = bh & 31;
    int hk = h >> 2;
    int q0 = blockIdx.x * 128;
    int tid = threadIdx.x;
    int qi = q0 + tid;

    __shared__ __align__(16) float Ks[32][64];
    __shared__ __align__(16) float Vs[32][64];

    ull q2[32];
    const float* qp = Q + (((size_t)b * NH + h) * TSEQ + qi) * DHEAD;
#pragma unroll
    for (int c = 0; c < 16; c++) {
        ulonglong2 t = *(const ulonglong2*)(qp + c * 4);
        q2[c * 2] = t.x; q2[c * 2 + 1] = t.y;
    }
    float m = -1e30f, l = 0.f;
    ull o2[32];
#pragma unroll
    for (int d = 0; d < 32; d++) o2[d] = 0ull;

    const float* kbase = Kg + (((size_t)b * NHK + hk) * TSEQ) * DHEAD;
    const float* vbase = Vg + (((size_t)b * NHK + hk) * TSEQ) * DHEAD;
    int nkt = (q0 + 128) / 32;

    for (int kt = 0; kt < nkt; kt++) {
        int kstart = kt * 32;
        __syncthreads();
#pragma unroll
        for (int i = 0; i < 4; i++) {
            int e = tid + i * 128;
            int row = e >> 4;
            int col = (e & 15) * 4;
            *(float4*)&Ks[row][col] = *(const float4*)(kbase + (size_t)(kstart + row) * 64 + col);
            *(float4*)&Vs[row][col] = *(const float4*)(vbase + (size_t)(kstart + row) * 64 + col);
        }
        __syncthreads();

        float s[32];
#pragma unroll
        for (int j = 0; j < 32; j++) {
            ull a0 = 0ull, a1 = 0ull, a2 = 0ull, a3 = 0ull;
#pragma unroll
            for (int c = 0; c < 8; c++) {
                ulonglong2 k01 = *(const ulonglong2*)&Ks[j][c * 8];
                ulonglong2 k23 = *(const ulonglong2*)&Ks[j][c * 8 + 4];
                fma2(a0, q2[c * 4 + 0], k01.x);
                fma2(a1, q2[c * 4 + 1], k01.y);
                fma2(a2, q2[c * 4 + 2], k23.x);
                fma2(a3, q2[c * 4 + 3], k23.y);
            }
            float2 f0 = upk2(a0), f1 = upk2(a1), f2 = upk2(a2), f3 = upk2(a3);
            float acc = ((f0.x + f0.y) + (f1.x + f1.y)) +
                        ((f2.x + f2.y) + (f3.x + f3.y));
            s[j] = (kstart + j <= qi) ? acc * 0.125f : -1e30f;
        }
        float mt = m;
#pragma unroll
        for (int j = 0; j < 32; j++) mt = fmaxf(mt, s[j]);
        float corr = __expf(m - mt);
        m = mt;
        l *= corr;
        ull c2 = pk2(corr);
#pragma unroll
        for (int d = 0; d < 32; d++) mul2(o2[d], c2);
#pragma unroll
        for (int j = 0; j < 32; j++) {
            float p = __expf(s[j] - m);
            l += p;
            ull p2 = pk2(p);
#pragma unroll
            for (int c = 0; c < 8; c++) {
                ulonglong2 v01 = *(const ulonglong2*)&Vs[j][c * 8];
                ulonglong2 v23 = *(const ulonglong2*)&Vs[j][c * 8 + 4];
                fma2(o2[c * 4 + 0], p2, v01.x);
                fma2(o2[c * 4 + 1], p2, v01.y);
                fma2(o2[c * 4 + 2], p2, v23.x);
                fma2(o2[c * 4 + 3], p2, v23.y);
            }
        }
    }
    float invl = 1.0f / l;
    float* op = Out + ((size_t)b * TSEQ + qi) * DMODEL + h * DHEAD;
#pragma unroll
    for (int d = 0; d < 32; d++) {
        float2 v = upk2(o2[d]);
        *(float2*)(op + d * 2) = make_float2(v.x * invl, v.y * invl);
    }
}

// ---------------------------------------------------------------------------
// Launch
// ---------------------------------------------------------------------------
extern "C" void kernel_launch(void* const* d_in, const int* in_sizes, int n_in,
                              void* d_out, int out_size) {
    const float* x     = (const float*)d_in[0];
    const int*   pos   = (const int*)d_in[1];
    const float* ln1   = (const float*)d_in[2];
    const float* ln2   = (const float*)d_in[3];
    const float* q_Us  = (const float*)d_in[4];
    const float* q_V   = (const float*)d_in[5];
    const float* k_Us  = (const float*)d_in[6];
    const float* k_V   = (const float*)d_in[7];
    const float* v_Us  = (const float*)d_in[8];
    const float* v_V   = (const float*)d_in[9];
    const float* o_Us  = (const float*)d_in[10];
    const float* o_V   = (const float*)d_in[11];
    const float* g_Us  = (const float*)d_in[12];
    const float* g_V   = (const float*)d_in[13];
    const float* u_Us  = (const float*)d_in[14];
    const float* u_V   = (const float*)d_in[15];
    const float* d_Us  = (const float*)d_in[16];
    const float* d_V   = (const float*)d_in[17];
    float* out = (float*)d_out;

    float* S = nullptr;
    cudaGetSymbolAddress((void**)&S, g_scratch);
    float* H  = S + OFF_H;
    float* Bb = S + OFF_B;
    float* C  = S + OFF_C;

    float* hbuf  = H;
    float* wc    = C;                        // 2304x2048
    float* qkvr  = Bb;                       // 2048x2304
    float* qb    = C;                        // 2*32*1024*64   (wc dead)
    float* kb    = C + 4194304;              // 2*8*1024*64
    float* vb    = C + 5242880;              // 2*8*1024*64
    float* attn  = H;                        // 2048x2048      (hbuf dead)
    float* ar    = Bb;                       // 2048x1024      (qkvr dead)
    float* gr    = Bb;                       // 2048x1024      (ar dead)
    float* ur    = Bb + 2097152;             // 2048x1024
    float* inner = C;                        // 512x8192       (qb/kb/vb dead)
    float* part  = C + 4194304;              // 4 x 512x1024
    float* dr    = H;                        // 2048x1024      (hbuf dead)

    // ---- attention sub-block ----
    rms_kernel<<<NTOK, 256>>>(x, ln1, hbuf);
    concat_qkv<<<4608, 256>>>(q_V, k_V, v_V, wc);
    gemm128<0><<<dim3(18, 16), 256>>>(hbuf, wc, nullptr, qkvr, 2304, 2048, 2048);
    proj2_kernel<<<dim3(16, 48), 256>>>(qkvr, q_Us, k_Us, v_Us, pos, qb, kb, vb);
    flash_kernel<<<dim3(8, 64), 128>>>(qb, kb, vb, attn);
    gemm128<0><<<dim3(8, 16), 256>>>(attn, o_V, nullptr, ar, 1024, 2048, 2048);
    gemm128<1><<<dim3(16, 16), 256>>>(ar, o_Us, x, out, 2048, 1024, 1024);

    // ---- MLP sub-block ----
    rms_kernel<<<NTOK, 256>>>(out, ln2, hbuf);
    gemm128<0><<<dim3(8, 16), 256>>>(hbuf, g_V, nullptr, gr, 1024, 2048, 2048);
    gemm128<0><<<dim3(8, 16), 256>>>(hbuf, u_V, nullptr, ur, 1024, 2048, 2048);

    for (int c = 0; c < NTOK / NCHUNK; c++) {
        const float* grc = gr + (size_t)c * NCHUNK * 1024;
        const float* urc = ur + (size_t)c * NCHUNK * 1024;
        gateup_kernel<<<dim3(128, 4), 256>>>(grc, urc, g_Us, u_Us, inner, 8192, 1024);
        gemm128<0><<<dim3(8, 4, 4), 256>>>(inner, d_V, nullptr, part, 1024, 8192, 2048);
        reduce4_kernel<<<512, 256>>>(part, dr + (size_t)c * NCHUNK * 1024);
    }
    gemm128<2><<<dim3(16, 16), 256>>>(dr, d_Us, nullptr, out, 2048, 1024, 1024);
}

// round 14
// speedup vs baseline: 1.9740x; 1.5149x over previous
#include <cuda_runtime.h>
#include <cuda_bf16.h>
#include <cstdint>

// ---------------------------------------------------------------------------
// FlashSVDLlamaBlock R12 (= R11 resubmit; R11 was an infra failure, never ran):
// base-ISA tensor cores (ldmatrix + mma.sync bf16, 3-pass hi/lo split
// precision) — tcgen05 unavailable (harness emits compute_103 PTX, no 'a'
// feature set). Plus R6 proj2 + packed-f32x2 flash.
//   B=2, T=1024, D=2048, H=32, HK=8, DH=64, R=48, RO=RFF=1024, INTER=8192
// Scratch (61 MB, phase-liveness reuse):
//   H [0..4,194,303]: hbuf -> attn -> hbuf -> dr
//   B [4,194,304..8,912,895]: qkvr -> ar -> gr/ur
//   C [8,912,896..15,204,351]: wc -> qb/kb/vb -> gate|inner|part (256-tok chunks)
// ---------------------------------------------------------------------------

#define NTOK 2048
#define DMODEL 2048
#define NH 32
#define NHK 8
#define DHEAD 64
#define RNK 48
#define TSEQ 1024
#define NCHUNK 256

#define OFF_H 0u
#define OFF_B 4194304u
#define OFF_C 8912896u
#define SCRATCH_TOTAL 15204352u

__device__ float g_scratch[SCRATCH_TOTAL];

typedef unsigned long long ull;

// ---- packed f32x2 helpers (flash attention) --------------------------------
__device__ __forceinline__ ull pk2(float v) {
    ull r; asm("mov.b64 %0, {%1, %1};" : "=l"(r) : "f"(v)); return r;
}
__device__ __forceinline__ void fma2(ull& c, ull a, ull b) {
    asm("fma.rn.f32x2 %0, %1, %2, %0;" : "+l"(c) : "l"(a), "l"(b));
}
__device__ __forceinline__ void mul2(ull& c, ull a) {
    asm("mul.rn.f32x2 %0, %0, %1;" : "+l"(c) : "l"(a));
}
__device__ __forceinline__ float2 upk2(ull v) {
    float2 r; asm("mov.b64 {%0, %1}, %2;" : "=f"(r.x), "=f"(r.y) : "l"(v)); return r;
}

// ---- tensor-core helpers (base ISA, sm_80+) --------------------------------
__device__ __forceinline__ uint32_t smem_to_u32(const void* p) {
    uint32_t a;
    asm("{ .reg .u64 t; cvta.to.shared.u64 t, %1; cvt.u32.u64 %0, t; }"
        : "=r"(a) : "l"(p));
    return a;
}
__device__ __forceinline__ void ldmx4(uint32_t* r, uint32_t addr) {
    asm volatile("ldmatrix.sync.aligned.m8n8.x4.shared.b16 {%0,%1,%2,%3}, [%4];"
                 : "=r"(r[0]), "=r"(r[1]), "=r"(r[2]), "=r"(r[3]) : "r"(addr));
}
__device__ __forceinline__ void ldmx2(uint32_t* r, uint32_t addr) {
    asm volatile("ldmatrix.sync.aligned.m8n8.x2.shared.b16 {%0,%1}, [%2];"
                 : "=r"(r[0]), "=r"(r[1]) : "r"(addr));
}
__device__ __forceinline__ void mma_bf16(float* c, const uint32_t* a,
                                         const uint32_t* b) {
    asm volatile(
        "mma.sync.aligned.m16n8k16.row.col.f32.bf16.bf16.f32 "
        "{%0,%1,%2,%3}, {%4,%5,%6,%7}, {%8,%9}, {%0,%1,%2,%3};"
        : "+f"(c[0]), "+f"(c[1]), "+f"(c[2]), "+f"(c[3])
        : "r"(a[0]), "r"(a[1]), "r"(a[2]), "r"(a[3]), "r"(b[0]), "r"(b[1]));
}
__device__ __forceinline__ uint32_t bf2pack(float x, float y) {
    __nv_bfloat162 h = __float22bfloat162_rn(make_float2(x, y));
    return *(uint32_t*)&h;
}

// ---------------------------------------------------------------------------
// mmbf16: C[n,m] = sum_k A[n,k]*W[m,k], tensor cores, 3-pass bf16 split.
//   MODE 0: C = d;  1: C = d + RG[n,m];  2: C += d;  3: C = silu(RG[n,m]) * d
// Tile 128(tok) x 128(feat), 8 warps (2x4), warp tile 64x32, BK=32.
// Smem rows stride 80 B (bank-conflict-free LDSM, no swizzle needed).
// Split-K via blockIdx.z (range Kt, out rows offset z*gridDim.y*128, MODE 0).
// ---------------------------------------------------------------------------
#define AHI 0
#define ALO 10240
#define WHI 20480
#define WLO 30720

template <int MODE>
__global__ void __launch_bounds__(256, 2) mmbf16(const float* __restrict__ A,
                                                 const float* __restrict__ W,
                                                 const float* __restrict__ RG,
                                                 float* __restrict__ C,
                                                 int M, int K, int Kt) {
    __shared__ __align__(16) char sm[40960];
    int tid = threadIdx.x;
    int wid = tid >> 5, lane = tid & 31;
    int m0 = blockIdx.x * 128, n0 = blockIdx.y * 128;
    size_t koff = (size_t)blockIdx.z * Kt;
    const float* Ap = A + (size_t)n0 * K + koff;
    const float* Wp = W + (size_t)m0 * K + koff;

    int wr = wid >> 2;          // warp row: 64 token-rows
    int wc = wid & 3;           // warp col: 32 feature-cols
    uint32_t sb = smem_to_u32(sm);

    // ldmatrix lane address offsets (bytes), row stride 80
    uint32_t aOff = (uint32_t)(wr * 64 + (lane & 7) + 8 * ((lane >> 3) & 1)) * 80
                  + ((lane >> 4) & 1) * 16;
    int lm = lane & 15;
    uint32_t bOff = (uint32_t)(wc * 32 + (lm & 7)) * 80 + ((lm >> 3) & 1) * 16;

    float c[4][4][4];
#pragma unroll
    for (int i = 0; i < 4; i++)
#pragma unroll
        for (int j = 0; j < 4; j++)
#pragma unroll
            for (int q = 0; q < 4; q++) c[i][j][q] = 0.f;

    int NC = Kt >> 5;
    for (int ch = 0; ch < NC; ch++) {
        // prefetch global chunk into regs (overlaps previous compute)
        float4 av[4], wv[4];
#pragma unroll
        for (int i = 0; i < 4; i++) {
            int s = tid + i * 256;          // 1024 float4-slots per tile
            int row = s >> 3;
            int c4 = (s & 7) * 4;
            av[i] = *(const float4*)(Ap + (size_t)row * K + ch * 32 + c4);
            wv[i] = *(const float4*)(Wp + (size_t)row * K + ch * 32 + c4);
        }
        __syncthreads();                     // previous compute done with smem
#pragma unroll
        for (int i = 0; i < 4; i++) {
            int s = tid + i * 256;
            int row = s >> 3;
            int c4 = (s & 7) * 4;
            uint32_t byte = (uint32_t)row * 80 + c4 * 2;
            float4 a = av[i], w = wv[i];
            // hi = bf16(x), lo = bf16(x - hi)
            float ahx = __bfloat162float(__float2bfloat16(a.x));
            float ahy = __bfloat162float(__float2bfloat16(a.y));
            float ahz = __bfloat162float(__float2bfloat16(a.z));
            float ahw = __bfloat162float(__float2bfloat16(a.w));
            float whx = __bfloat162float(__float2bfloat16(w.x));
            float why = __bfloat162float(__float2bfloat16(w.y));
            float whz = __bfloat162float(__float2bfloat16(w.z));
            float whw = __bfloat162float(__float2bfloat16(w.w));
            *(uint2*)(sm + AHI + byte) =
                make_uint2(bf2pack(a.x, a.y), bf2pack(a.z, a.w));
            *(uint2*)(sm + ALO + byte) =
                make_uint2(bf2pack(a.x - ahx, a.y - ahy), bf2pack(a.z - ahz, a.w - ahw));
            *(uint2*)(sm + WHI + byte) =
                make_uint2(bf2pack(w.x, w.y), bf2pack(w.z, w.w));
            *(uint2*)(sm + WLO + byte) =
                make_uint2(bf2pack(w.x - whx, w.y - why), bf2pack(w.z - whz, w.w - whw));
        }
        __syncthreads();
#pragma unroll
        for (int k16 = 0; k16 < 2; k16++) {
            uint32_t kb = k16 * 32;          // 16 bf16 = 32 bytes
            uint32_t ah[4][4], al[4][4];
#pragma unroll
            for (int mi = 0; mi < 4; mi++) {
                ldmx4(ah[mi], sb + AHI + aOff + mi * 1280 + kb);
                ldmx4(al[mi], sb + ALO + aOff + mi * 1280 + kb);
            }
#pragma unroll
            for (int ni = 0; ni < 4; ni++) {
                uint32_t bh[2], bl[2];
                ldmx2(bh, sb + WHI + bOff + ni * 640 + kb);
                ldmx2(bl, sb + WLO + bOff + ni * 640 + kb);
#pragma unroll
                for (int mi = 0; mi < 4; mi++) {
                    mma_bf16(c[mi][ni], ah[mi], bh);
                    mma_bf16(c[mi][ni], ah[mi], bl);
                    mma_bf16(c[mi][ni], al[mi], bh);
                }
            }
        }
    }

    // epilogue: D fragment c0..c3 -> rows (g, g+8), cols (2t, 2t+1)
    int g = lane >> 2, t = lane & 3;
    int zrow = blockIdx.z * (gridDim.y << 7);
#pragma unroll
    for (int mi = 0; mi < 4; mi++) {
#pragma unroll
        for (int ni = 0; ni < 4; ni++) {
            int row0 = n0 + wr * 64 + mi * 16 + g;
            int col = m0 + wc * 32 + ni * 8 + t * 2;
            size_t i0 = (size_t)(zrow + row0) * M + col;
            size_t i1 = i0 + (size_t)8 * M;
            float2 v0 = make_float2(c[mi][ni][0], c[mi][ni][1]);
            float2 v1 = make_float2(c[mi][ni][2], c[mi][ni][3]);
            if (MODE == 1) {
                float2 r0 = *(const float2*)&RG[i0];
                float2 r1 = *(const float2*)&RG[i1];
                v0.x += r0.x; v0.y += r0.y; v1.x += r1.x; v1.y += r1.y;
            }
            if (MODE == 2) {
                float2 r0 = *(const float2*)&C[i0];
                float2 r1 = *(const float2*)&C[i1];
                v0.x += r0.x; v0.y += r0.y; v1.x += r1.x; v1.y += r1.y;
            }
            if (MODE == 3) {
                float2 g0 = *(const float2*)&RG[i0];
                float2 g1 = *(const float2*)&RG[i1];
                v0.x *= g0.x / (1.0f + __expf(-g0.x));
                v0.y *= g0.y / (1.0f + __expf(-g0.y));
                v1.x *= g1.x / (1.0f + __expf(-g1.x));
                v1.y *= g1.y / (1.0f + __expf(-g1.y));
            }
            *(float2*)&C[i0] = v0;
            *(float2*)&C[i1] = v1;
        }
    }
}

// ---------------------------------------------------------------------------
// RMSNorm
// ---------------------------------------------------------------------------
__global__ void __launch_bounds__(256) rms_kernel(const float* __restrict__ x,
                                                  const float* __restrict__ w,
                                                  float* __restrict__ out) {
    int n = blockIdx.x;
    int tid = threadIdx.x;
    const float4* xr = (const float4*)(x + (size_t)n * DMODEL);
    float4 loc[2];
    float ss = 0.f;
#pragma unroll
    for (int i = 0; i < 2; i++) {
        float4 v = xr[tid + i * 256];
        loc[i] = v;
        ss += v.x * v.x + v.y * v.y + v.z * v.z + v.w * v.w;
    }
#pragma unroll
    for (int off = 16; off; off >>= 1)
        ss += __shfl_xor_sync(0xffffffffu, ss, off);
    __shared__ float red[8];
    if ((tid & 31) == 0) red[tid >> 5] = ss;
    __syncthreads();
    float tot = red[0] + red[1] + red[2] + red[3] + red[4] + red[5] + red[6] + red[7];
    float inv = rsqrtf(tot * (1.0f / (float)DMODEL) + 1e-5f);
    const float4* w4 = (const float4*)w;
    float4* o4 = (float4*)(out + (size_t)n * DMODEL);
#pragma unroll
    for (int i = 0; i < 2; i++) {
        int idx = tid + i * 256;
        float4 wv = w4[idx];
        float4 v = loc[i];
        o4[idx] = make_float4(v.x * inv * wv.x, v.y * inv * wv.y,
                              v.z * inv * wv.z, v.w * inv * wv.w);
    }
}

// ---------------------------------------------------------------------------
// qkv weight concat: wc = [q_V(1536x2048); k_V(384x2048); v_V(384x2048)]
// ---------------------------------------------------------------------------
__global__ void __launch_bounds__(256) concat_qkv(const float* __restrict__ q,
                                                  const float* __restrict__ k,
                                                  const float* __restrict__ v,
                                                  float* __restrict__ wc) {
    int i = blockIdx.x * 256 + threadIdx.x;
    float4 val;
    if (i < 786432) val = ((const float4*)q)[i];
    else if (i < 983040) val = ((const float4*)k)[i - 786432];
    else val = ((const float4*)v)[i - 983040];
    ((float4*)wc)[i] = val;
}

// ---------------------------------------------------------------------------
// split-K reduce: dst[i] = sum_{p<8} part[p*262144 + i]   (256x1024 floats)
// ---------------------------------------------------------------------------
__global__ void __launch_bounds__(256) reduce8_kernel(const float* __restrict__ part,
                                                      float* __restrict__ dst) {
    int i = blockIdx.x * 256 + threadIdx.x;
    const float4* p = (const float4*)part;
    float4 s = p[i];
#pragma unroll
    for (int j = 1; j < 8; j++) {
        float4 v = p[i + j * 65536];
        s.x += v.x; s.y += v.y; s.z += v.z; s.w += v.w;
    }
    ((float4*)dst)[i] = s;
}

// ---------------------------------------------------------------------------
// Batched per-head Us projection + fused RoPE (R6 version).
// ---------------------------------------------------------------------------
__global__ void __launch_bounds__(256) proj2_kernel(
    const float* __restrict__ Rv,
    const float* __restrict__ q_Us, const float* __restrict__ k_Us,
    const float* __restrict__ v_Us,
    const int* __restrict__ pos_ids,
    float* __restrict__ qb, float* __restrict__ kb, float* __restrict__ vb) {
    int hidx = blockIdx.y;
    int n0 = blockIdx.x * 128;
    int tid = threadIdx.x;
    __shared__ float Rvs[48][128];
    __shared__ float Uss[48][64];

#pragma unroll
    for (int i = 0; i < 6; i++) {
        int f = tid + i * 256;
        int r = f / 12, c4 = (f % 12) * 4;
        float4 v = *(const float4*)&Rv[(size_t)(n0 + r) * 2304 + hidx * 48 + c4];
        Rvs[c4 + 0][r] = v.x; Rvs[c4 + 1][r] = v.y;
        Rvs[c4 + 2][r] = v.z; Rvs[c4 + 3][r] = v.w;
    }
    const float* Us = (hidx < 32) ? q_Us + (size_t)hidx * 3072
                    : (hidx < 40) ? k_Us + (size_t)(hidx - 32) * 3072
                                  : v_Us + (size_t)(hidx - 40) * 3072;
#pragma unroll
    for (int i = 0; i < 3; i++) {
        int f = tid + i * 256;
        int dh = f / 12, c4 = (f % 12) * 4;
        float4 v = *(const float4*)&Us[dh * 48 + c4];
        Uss[c4 + 0][dh] = v.x; Uss[c4 + 1][dh] = v.y;
        Uss[c4 + 2][dh] = v.z; Uss[c4 + 3][dh] = v.w;
    }
    __syncthreads();

    int tx = tid & 7;
    int ty = tid >> 3;
    float acc[4][8];
#pragma unroll
    for (int i = 0; i < 4; i++)
#pragma unroll
        for (int j = 0; j < 8; j++) acc[i][j] = 0.f;

#pragma unroll 8
    for (int k = 0; k < 48; k++) {
        float4 a = *(const float4*)&Rvs[k][ty * 4];
        float4 w0 = *(const float4*)&Uss[k][tx * 8];
        float4 w1 = *(const float4*)&Uss[k][tx * 8 + 4];
        float av[4] = {a.x, a.y, a.z, a.w};
        float wv[8] = {w0.x, w0.y, w0.z, w0.w, w1.x, w1.y, w1.z, w1.w};
#pragma unroll
        for (int i = 0; i < 4; i++)
#pragma unroll
            for (int j = 0; j < 8; j++) acc[i][j] += av[i] * wv[j];
    }

    float prt[4][8];
#pragma unroll
    for (int i = 0; i < 4; i++)
#pragma unroll
        for (int j = 0; j < 8; j++)
            prt[i][j] = __shfl_xor_sync(0xffffffffu, acc[i][j], 4);

    bool dorope = (hidx < 40);
    float sgn = (tx < 4) ? -1.f : 1.f;
    float invf[4];
    if (dorope) {
#pragma unroll
        for (int fj = 0; fj < 4; fj++)
            invf[fj] = expf(-(float)(tx * 4 + fj) * (9.210340371976184f / 32.0f));
    }

    float* outp;
    int hh, nh;
    if (hidx < 32)      { outp = qb; hh = hidx;      nh = NH;  }
    else if (hidx < 40) { outp = kb; hh = hidx - 32; nh = NHK; }
    else                { outp = vb; hh = hidx - 40; nh = NHK; }

#pragma unroll
    for (int i = 0; i < 4; i++) {
        int n = n0 + ty * 4 + i;
        int b = n >> 10;
        int t = n & 1023;
        float vals[8];
        if (dorope) {
            float pos = (float)pos_ids[t];
#pragma unroll
            for (int fj = 0; fj < 4; fj++) {
                float ang = pos * invf[fj];
                float c = cosf(ang), s = sinf(ang);
                vals[fj * 2 + 0] = acc[i][fj * 2 + 0] * c + sgn * prt[i][fj * 2 + 0] * s;
                vals[fj * 2 + 1] = acc[i][fj * 2 + 1] * c + sgn * prt[i][fj * 2 + 1] * s;
            }
        } else {
#pragma unroll
            for (int j = 0; j < 8; j++) vals[j] = acc[i][j];
        }
        float* op = outp + (((size_t)b * nh + hh) * TSEQ + t) * DHEAD + tx * 8;
        *(float4*)op       = make_float4(vals[0], vals[1], vals[2], vals[3]);
        *(float4*)(op + 4) = make_float4(vals[4], vals[5], vals[6], vals[7]);
    }
}

// ---------------------------------------------------------------------------
// Causal flash attention, packed f32x2 + __expf (R6 version).
// ---------------------------------------------------------------------------
__global__ void __launch_bounds__(128) flash_kernel(const float* __restrict__ Q,
                                                    const float* __restrict__ Kg,
                                                    const float* __restrict__ Vg,
                                                    float* __restrict__ Out) {
    int bh = blockIdx.y;
    int b = bh >> 5;
    int h = bh & 31;
    int hk = h >> 2;
    int q0 = blockIdx.x * 128;
    int tid = threadIdx.x;
    int qi = q0 + tid;

    __shared__ __align__(16) float Ks[32][64];
    __shared__ __align__(16) float Vs[32][64];

    ull q2[32];
    const float* qp = Q + (((size_t)b * NH + h) * TSEQ + qi) * DHEAD;
#pragma unroll
    for (int c = 0; c < 16; c++) {
        ulonglong2 t = *(const ulonglong2*)(qp + c * 4);
        q2[c * 2] = t.x; q2[c * 2 + 1] = t.y;
    }
    float m = -1e30f, l = 0.f;
    ull o2[32];
#pragma unroll
    for (int d = 0; d < 32; d++) o2[d] = 0ull;

    const float* kbase = Kg + (((size_t)b * NHK + hk) * TSEQ) * DHEAD;
    const float* vbase = Vg + (((size_t)b * NHK + hk) * TSEQ) * DHEAD;
    int nkt = (q0 + 128) / 32;

    for (int kt = 0; kt < nkt; kt++) {
        int kstart = kt * 32;
        __syncthreads();
#pragma unroll
        for (int i = 0; i < 4; i++) {
            int e = tid + i * 128;
            int row = e >> 4;
            int col = (e & 15) * 4;
            *(float4*)&Ks[row][col] = *(const float4*)(kbase + (size_t)(kstart + row) * 64 + col);
            *(float4*)&Vs[row][col] = *(const float4*)(vbase + (size_t)(kstart + row) * 64 + col);
        }
        __syncthreads();

        float s[32];
#pragma unroll
        for (int j = 0; j < 32; j++) {
            ull a0 = 0ull, a1 = 0ull, a2 = 0ull, a3 = 0ull;
#pragma unroll
            for (int c = 0; c < 8; c++) {
                ulonglong2 k01 = *(const ulonglong2*)&Ks[j][c * 8];
                ulonglong2 k23 = *(const ulonglong2*)&Ks[j][c * 8 + 4];
                fma2(a0, q2[c * 4 + 0], k01.x);
                fma2(a1, q2[c * 4 + 1], k01.y);
                fma2(a2, q2[c * 4 + 2], k23.x);
                fma2(a3, q2[c * 4 + 3], k23.y);
            }
            float2 f0 = upk2(a0), f1 = upk2(a1), f2 = upk2(a2), f3 = upk2(a3);
            float acc = ((f0.x + f0.y) + (f1.x + f1.y)) +
                        ((f2.x + f2.y) + (f3.x + f3.y));
            s[j] = (kstart + j <= qi) ? acc * 0.125f : -1e30f;
        }
        float mt = m;
#pragma unroll
        for (int j = 0; j < 32; j++) mt = fmaxf(mt, s[j]);
        float corr = __expf(m - mt);
        m = mt;
        l *= corr;
        ull c2 = pk2(corr);
#pragma unroll
        for (int d = 0; d < 32; d++) mul2(o2[d], c2);
#pragma unroll
        for (int j = 0; j < 32; j++) {
            float p = __expf(s[j] - m);
            l += p;
            ull p2 = pk2(p);
#pragma unroll
            for (int c = 0; c < 8; c++) {
                ulonglong2 v01 = *(const ulonglong2*)&Vs[j][c * 8];
                ulonglong2 v23 = *(const ulonglong2*)&Vs[j][c * 8 + 4];
                fma2(o2[c * 4 + 0], p2, v01.x);
                fma2(o2[c * 4 + 1], p2, v01.y);
                fma2(o2[c * 4 + 2], p2, v23.x);
                fma2(o2[c * 4 + 3], p2, v23.y);
            }
        }
    }
    float invl = 1.0f / l;
    float* op = Out + ((size_t)b * TSEQ + qi) * DMODEL + h * DHEAD;
#pragma unroll
    for (int d = 0; d < 32; d++) {
        float2 v = upk2(o2[d]);
        *(float2*)(op + d * 2) = make_float2(v.x * invl, v.y * invl);
    }
}

// ---------------------------------------------------------------------------
// Launch
// ---------------------------------------------------------------------------
extern "C" void kernel_launch(void* const* d_in, const int* in_sizes, int n_in,
                              void* d_out, int out_size) {
    const float* x     = (const float*)d_in[0];
    const int*   pos   = (const int*)d_in[1];
    const float* ln1   = (const float*)d_in[2];
    const float* ln2   = (const float*)d_in[3];
    const float* q_Us  = (const float*)d_in[4];
    const float* q_V   = (const float*)d_in[5];
    const float* k_Us  = (const float*)d_in[6];
    const float* k_V   = (const float*)d_in[7];
    const float* v_Us  = (const float*)d_in[8];
    const float* v_V   = (const float*)d_in[9];
    const float* o_Us  = (const float*)d_in[10];
    const float* o_V   = (const float*)d_in[11];
    const float* g_Us  = (const float*)d_in[12];
    const float* g_V   = (const float*)d_in[13];
    const float* u_Us  = (const float*)d_in[14];
    const float* u_V   = (const float*)d_in[15];
    const float* d_Us  = (const float*)d_in[16];
    const float* d_V   = (const float*)d_in[17];
    float* out = (float*)d_out;

    float* S = nullptr;
    cudaGetSymbolAddress((void**)&S, g_scratch);
    float* H  = S + OFF_H;
    float* Bb = S + OFF_B;
    float* C  = S + OFF_C;

    float* hbuf  = H;
    float* wc    = C;                        // 2304x2048
    float* qkvr  = Bb;                       // 2048x2304
    float* qb    = C;                        // 2*32*1024*64   (wc dead)
    float* kb    = C + 4194304;              // 2*8*1024*64
    float* vb    = C + 5242880;              // 2*8*1024*64
    float* attn  = H;                        // 2048x2048      (hbuf dead)
    float* ar    = Bb;                       // 2048x1024      (qkvr dead)
    float* gr    = Bb;                       // 2048x1024      (ar dead)
    float* ur    = Bb + 2097152;             // 2048x1024
    float* gate  = C;                        // 256x8192       (qb/kb/vb dead)
    float* inner = C + 2097152;              // 256x8192
    float* part  = C + 4194304;              // 8 x 256x1024
    float* dr    = H;                        // 2048x1024      (hbuf dead)

    // ---- attention sub-block ----
    rms_kernel<<<NTOK, 256>>>(x, ln1, hbuf);
    concat_qkv<<<4608, 256>>>(q_V, k_V, v_V, wc);
    mmbf16<0><<<dim3(18, 16), 256>>>(hbuf, wc, nullptr, qkvr, 2304, 2048, 2048);
    proj2_kernel<<<dim3(16, 48), 256>>>(qkvr, q_Us, k_Us, v_Us, pos, qb, kb, vb);
    flash_kernel<<<dim3(8, 64), 128>>>(qb, kb, vb, attn);
    mmbf16<0><<<dim3(8, 16), 256>>>(attn, o_V, nullptr, ar, 1024, 2048, 2048);
    mmbf16<1><<<dim3(16, 16), 256>>>(ar, o_Us, x, out, 2048, 1024, 1024);

    // ---- MLP sub-block ----
    rms_kernel<<<NTOK, 256>>>(out, ln2, hbuf);
    mmbf16<0><<<dim3(8, 16), 256>>>(hbuf, g_V, nullptr, gr, 1024, 2048, 2048);
    mmbf16<0><<<dim3(8, 16), 256>>>(hbuf, u_V, nullptr, ur, 1024, 2048, 2048);

    for (int c = 0; c < NTOK / NCHUNK; c++) {
        const float* grc = gr + (size_t)c * NCHUNK * 1024;
        const float* urc = ur + (size_t)c * NCHUNK * 1024;
        float* drc = dr + (size_t)c * NCHUNK * 1024;
        mmbf16<0><<<dim3(64, 2), 256>>>(grc, g_Us, nullptr, gate, 8192, 1024, 1024);
        mmbf16<3><<<dim3(64, 2), 256>>>(urc, u_Us, gate, inner, 8192, 1024, 1024);
        mmbf16<0><<<dim3(8, 2, 8), 256>>>(inner, d_V, nullptr, part, 1024, 8192, 1024);
        reduce8_kernel<<<256, 256>>>(part, drc);
    }
    mmbf16<2><<<dim3(16, 16), 256>>>(dr, d_Us, nullptr, out, 2048, 1024, 1024);
}